// round 2
// baseline (speedup 1.0000x reference)
#include <cuda_runtime.h>
#include <cuda_bf16.h>

#define N_NODES 50000
#define D 128
#define N_CLASSES 40

// Scratch (static device globals — no allocations allowed).
// NOTE: only referenced from DEVICE code. Referencing these symbols in host
// code yields the host shadow address (silently readable on GB300 via ATS!).
__device__ float g_h[N_NODES * D];    // gather source for scatter
__device__ float g_acc[N_NODES * D];  // h + aggregated messages

// ---------------------------------------------------------------------------
// Copy input x into both scratch buffers (g_acc accumulates messages on top)
// ---------------------------------------------------------------------------
__global__ void gcn_copy_kernel(const float* __restrict__ x) {
    int i = blockIdx.x * blockDim.x + threadIdx.x;
    if (i < N_NODES * D / 4) {
        float4 v = ((const float4*)x)[i];
        ((float4*)g_h)[i] = v;
        ((float4*)g_acc)[i] = v;
    }
}

// ---------------------------------------------------------------------------
// Scatter: one warp per edge. Lane reads float4 of source row, vector-red
// (red.global.add.v4.f32) into destination row of g_acc.
// ---------------------------------------------------------------------------
__global__ void gcn_scatter_kernel(const int* __restrict__ src,
                                   const int* __restrict__ dst,
                                   int n_edges) {
    int e = (int)((blockIdx.x * (unsigned)blockDim.x + threadIdx.x) >> 5);
    if (e >= n_edges) return;
    int lane = threadIdx.x & 31;
    int s = __ldg(src + e);
    int d = __ldg(dst + e);
    float4 v = *(const float4*)(g_h + (size_t)s * D + lane * 4);
    float* p = g_acc + (size_t)d * D + lane * 4;
    asm volatile("red.global.add.v4.f32 [%0], {%1, %2, %3, %4};"
                 :: "l"(p), "f"(v.x), "f"(v.y), "f"(v.z), "f"(v.w)
                 : "memory");
}

// ---------------------------------------------------------------------------
// Tiled fp32 GEMM: out[n, j] = act( sum_k g_acc[n,k] * W[j,k] + bias[j] )
// A operand is ALWAYS g_acc (read via device-side symbol, not a host arg).
// BM=64 rows/block, 256 threads, each computes 4 rows x TN cols.
// If DUAL: write result to g_h AND g_acc (sets up next layer); else to `out`.
// ---------------------------------------------------------------------------
template <int BN, int TN, bool RELU, bool DUAL>
__global__ void gcn_gemm_kernel(const float* __restrict__ W,
                                const float* __restrict__ bias,
                                float* __restrict__ out,
                                int n_out, int ldo) {
    constexpr int BM = 64;
    constexpr int K = D;
    constexpr int LDA = K + 4;    // 132, float4-friendly pad, no bank conflicts
    constexpr int LDB = BN + 4;
    extern __shared__ float sm[];
    float* As = sm;               // [BM][LDA]
    float* Bs = sm + BM * LDA;    // [K][LDB]  (W transposed: Bs[k][j])

    int tid = threadIdx.x;
    int row0 = blockIdx.x * BM;

    // Load W (transposed into Bs).
    for (int i = tid; i < BN * K; i += 256) {
        int j = i / K, k = i % K;
        float v = (j < n_out) ? __ldg(W + j * K + k) : 0.f;
        Bs[k * LDB + j] = v;
    }
    // Load A tile from g_acc (float4).
    for (int i = tid * 4; i < BM * K; i += 256 * 4) {
        int r = i / K, k = i % K;
        int g = row0 + r;
        float4 v = (g < N_NODES) ? *(const float4*)(g_acc + (size_t)g * K + k)
                                 : make_float4(0.f, 0.f, 0.f, 0.f);
        *(float4*)(As + r * LDA + k) = v;
    }
    __syncthreads();

    int tc = tid & 15;   // 16 col-groups
    int tr = tid >> 4;   // 16 row-groups of 4 rows

    float acc[4][TN];
#pragma unroll
    for (int ii = 0; ii < 4; ii++)
#pragma unroll
        for (int jj = 0; jj < TN; jj++) acc[ii][jj] = 0.f;

#pragma unroll 4
    for (int k = 0; k < K; k++) {
        float a[4], b[TN];
#pragma unroll
        for (int ii = 0; ii < 4; ii++) a[ii] = As[(tr * 4 + ii) * LDA + k];
#pragma unroll
        for (int jj = 0; jj < TN; jj++) b[jj] = Bs[k * LDB + tc + 16 * jj];
#pragma unroll
        for (int ii = 0; ii < 4; ii++)
#pragma unroll
            for (int jj = 0; jj < TN; jj++)
                acc[ii][jj] = fmaf(a[ii], b[jj], acc[ii][jj]);
    }

#pragma unroll
    for (int ii = 0; ii < 4; ii++) {
        int g = row0 + tr * 4 + ii;
        if (g >= N_NODES) continue;
#pragma unroll
        for (int jj = 0; jj < TN; jj++) {
            int j = tc + 16 * jj;
            if (j >= n_out) continue;
            float v = acc[ii][jj] + __ldg(bias + j);
            if (RELU) v = fmaxf(v, 0.f);
            if (DUAL) {
                g_h[(size_t)g * D + j] = v;
                g_acc[(size_t)g * D + j] = v;
            } else {
                out[(size_t)g * ldo + j] = v;
            }
        }
    }
}

// ---------------------------------------------------------------------------
extern "C" void kernel_launch(void* const* d_in, const int* in_sizes, int n_in,
                              void* d_out, int out_size) {
    const float* x  = (const float*)d_in[0];
    const int* src  = (const int*)d_in[1];
    const int* dst  = (const int*)d_in[2];
    const float* W0 = (const float*)d_in[3];
    const float* b0 = (const float*)d_in[4];
    const float* W1 = (const float*)d_in[5];
    const float* b1 = (const float*)d_in[6];
    const float* W2 = (const float*)d_in[7];
    const float* b2 = (const float*)d_in[8];
    float* out = (float*)d_out;
    int n_edges = in_sizes[1];

    constexpr int SMEM_BIG   = (64 * 132 + 128 * 132) * 4;  // 101376 B
    constexpr int SMEM_SMALL = (64 * 132 + 128 * 68) * 4;   //  68608 B
    static bool attr_done = false;
    if (!attr_done) {
        cudaFuncSetAttribute(gcn_gemm_kernel<128, 8, true, true>,
                             cudaFuncAttributeMaxDynamicSharedMemorySize, SMEM_BIG);
        cudaFuncSetAttribute(gcn_gemm_kernel<64, 4, false, false>,
                             cudaFuncAttributeMaxDynamicSharedMemorySize, SMEM_SMALL);
        attr_done = true;
    }

    int copy_blocks = (N_NODES * D / 4 + 255) / 256;
    int scat_blocks = (n_edges * 32 + 255) / 256;
    int gemm_blocks = (N_NODES + 63) / 64;

    // Layer 0
    gcn_copy_kernel<<<copy_blocks, 256>>>(x);
    gcn_scatter_kernel<<<scat_blocks, 256>>>(src, dst, n_edges);
    gcn_gemm_kernel<128, 8, true, true><<<gemm_blocks, 256, SMEM_BIG>>>(
        W0, b0, nullptr, D, D);
    // Layer 1
    gcn_scatter_kernel<<<scat_blocks, 256>>>(src, dst, n_edges);
    gcn_gemm_kernel<128, 8, true, true><<<gemm_blocks, 256, SMEM_BIG>>>(
        W1, b1, nullptr, D, D);
    // Layer 2 (40-class head, no activation, writes d_out)
    gcn_scatter_kernel<<<scat_blocks, 256>>>(src, dst, n_edges);
    gcn_gemm_kernel<64, 4, false, false><<<gemm_blocks, 256, SMEM_SMALL>>>(
        W2, b2, out, N_CLASSES, N_CLASSES);
}

// round 3
// speedup vs baseline: 1.1096x; 1.1096x over previous
#include <cuda_runtime.h>
#include <cuda_bf16.h>

#define N_NODES 50000
#define N_EDGES_MAX 600000
#define D 128
#define N_CLASSES 40

// Scratch (static device globals — no allocations allowed).
// Only referenced from DEVICE code (host shadow deref is silent on GB300/ATS).
__device__ float g_h[N_NODES * D];     // current layer activations
__device__ float g_acc[N_NODES * D];   // h + aggregated messages
__device__ int   g_cnt[N_NODES];       // in-degree histogram
__device__ int   g_row[N_NODES + 1];   // CSR row pointers (by dst)
__device__ int   g_cur[N_NODES];       // fill cursors
__device__ int   g_esrc[N_EDGES_MAX];  // CSR column indices (src nodes)

// ---------------------------------------------------------------------------
__global__ void gcn_copy_kernel(const float* __restrict__ x) {
    int i = blockIdx.x * blockDim.x + threadIdx.x;
    if (i < N_NODES * D / 4)
        ((float4*)g_h)[i] = ((const float4*)x)[i];
}

__global__ void gcn_zero_cnt_kernel() {
    int i = blockIdx.x * blockDim.x + threadIdx.x;
    if (i < N_NODES) g_cnt[i] = 0;
}

__global__ void gcn_hist_kernel(const int* __restrict__ dst, int n_edges) {
    int e = blockIdx.x * blockDim.x + threadIdx.x;
    if (e < n_edges) atomicAdd(&g_cnt[dst[e]], 1);
}

// Single-block exclusive scan of g_cnt -> g_row (and g_cur copy).
__global__ void gcn_scan_kernel() {
    __shared__ int part[1024];
    const int CH = (N_NODES + 1023) / 1024;  // 49
    int t = threadIdx.x;
    int base = t * CH;
    int s = 0;
    for (int i = 0; i < CH; i++) {
        int idx = base + i;
        if (idx < N_NODES) s += g_cnt[idx];
    }
    part[t] = s;
    __syncthreads();
    for (int off = 1; off < 1024; off <<= 1) {
        int v = (t >= off) ? part[t - off] : 0;
        __syncthreads();
        part[t] += v;
        __syncthreads();
    }
    int pre = (t == 0) ? 0 : part[t - 1];
    for (int i = 0; i < CH; i++) {
        int idx = base + i;
        if (idx < N_NODES) {
            g_row[idx] = pre;
            g_cur[idx] = pre;
            pre += g_cnt[idx];
        }
    }
    if (t == 1023) g_row[N_NODES] = pre;
}

__global__ void gcn_fill_kernel(const int* __restrict__ src,
                                const int* __restrict__ dst, int n_edges) {
    int e = blockIdx.x * blockDim.x + threadIdx.x;
    if (e < n_edges) {
        int pos = atomicAdd(&g_cur[dst[e]], 1);
        g_esrc[pos] = src[e];
    }
}

// ---------------------------------------------------------------------------
// Gather: one warp per node. g_acc[n] = g_h[n] + sum_{s in nbrs(n)} g_h[s].
// Unrolled x4 over neighbors for MLP.
// ---------------------------------------------------------------------------
__global__ void gcn_gather_kernel() {
    int node = blockIdx.x * (blockDim.x >> 5) + (threadIdx.x >> 5);
    if (node >= N_NODES) return;
    int lane = threadIdx.x & 31;
    int beg = g_row[node];
    int end = g_row[node + 1];
    float4 acc = *(const float4*)(g_h + (size_t)node * D + lane * 4);  // self
    int i = beg;
    for (; i + 4 <= end; i += 4) {
        int s0 = g_esrc[i], s1 = g_esrc[i + 1], s2 = g_esrc[i + 2], s3 = g_esrc[i + 3];
        float4 v0 = *(const float4*)(g_h + (size_t)s0 * D + lane * 4);
        float4 v1 = *(const float4*)(g_h + (size_t)s1 * D + lane * 4);
        float4 v2 = *(const float4*)(g_h + (size_t)s2 * D + lane * 4);
        float4 v3 = *(const float4*)(g_h + (size_t)s3 * D + lane * 4);
        acc.x += v0.x + v1.x + v2.x + v3.x;
        acc.y += v0.y + v1.y + v2.y + v3.y;
        acc.z += v0.z + v1.z + v2.z + v3.z;
        acc.w += v0.w + v1.w + v2.w + v3.w;
    }
    for (; i < end; i++) {
        int s = g_esrc[i];
        float4 v = *(const float4*)(g_h + (size_t)s * D + lane * 4);
        acc.x += v.x; acc.y += v.y; acc.z += v.z; acc.w += v.w;
    }
    *(float4*)(g_acc + (size_t)node * D + lane * 4) = acc;
}

// ---------------------------------------------------------------------------
// Tiled fp32 GEMM: res[n, j] = act( sum_k g_acc[n,k] * W[j,k] + bias[j] )
// If TO_GH: result -> g_h (next layer input); else -> out (row stride ldo).
// ---------------------------------------------------------------------------
template <int BN, int TN, bool RELU, bool TO_GH>
__global__ void gcn_gemm_kernel(const float* __restrict__ W,
                                const float* __restrict__ bias,
                                float* __restrict__ out,
                                int n_out, int ldo) {
    constexpr int BM = 64;
    constexpr int K = D;
    constexpr int LDA = K + 4;
    constexpr int LDB = BN + 4;
    extern __shared__ float sm[];
    float* As = sm;               // [BM][LDA]
    float* Bs = sm + BM * LDA;    // [K][LDB]

    int tid = threadIdx.x;
    int row0 = blockIdx.x * BM;

    for (int i = tid; i < BN * K; i += 256) {
        int j = i / K, k = i % K;
        float v = (j < n_out) ? __ldg(W + j * K + k) : 0.f;
        Bs[k * LDB + j] = v;
    }
    for (int i = tid * 4; i < BM * K; i += 256 * 4) {
        int r = i / K, k = i % K;
        int g = row0 + r;
        float4 v = (g < N_NODES) ? *(const float4*)(g_acc + (size_t)g * K + k)
                                 : make_float4(0.f, 0.f, 0.f, 0.f);
        *(float4*)(As + r * LDA + k) = v;
    }
    __syncthreads();

    int tc = tid & 15;
    int tr = tid >> 4;

    float acc[4][TN];
#pragma unroll
    for (int ii = 0; ii < 4; ii++)
#pragma unroll
        for (int jj = 0; jj < TN; jj++) acc[ii][jj] = 0.f;

#pragma unroll 4
    for (int k = 0; k < K; k++) {
        float a[4], b[TN];
#pragma unroll
        for (int ii = 0; ii < 4; ii++) a[ii] = As[(tr * 4 + ii) * LDA + k];
#pragma unroll
        for (int jj = 0; jj < TN; jj++) b[jj] = Bs[k * LDB + tc + 16 * jj];
#pragma unroll
        for (int ii = 0; ii < 4; ii++)
#pragma unroll
            for (int jj = 0; jj < TN; jj++)
                acc[ii][jj] = fmaf(a[ii], b[jj], acc[ii][jj]);
    }

#pragma unroll
    for (int ii = 0; ii < 4; ii++) {
        int g = row0 + tr * 4 + ii;
        if (g >= N_NODES) continue;
#pragma unroll
        for (int jj = 0; jj < TN; jj++) {
            int j = tc + 16 * jj;
            if (j >= n_out) continue;
            float v = acc[ii][jj] + __ldg(bias + j);
            if (RELU) v = fmaxf(v, 0.f);
            if (TO_GH) g_h[(size_t)g * D + j] = v;
            else       out[(size_t)g * ldo + j] = v;
        }
    }
}

// ---------------------------------------------------------------------------
extern "C" void kernel_launch(void* const* d_in, const int* in_sizes, int n_in,
                              void* d_out, int out_size) {
    const float* x  = (const float*)d_in[0];
    const int* src  = (const int*)d_in[1];
    const int* dst  = (const int*)d_in[2];
    const float* W0 = (const float*)d_in[3];
    const float* b0 = (const float*)d_in[4];
    const float* W1 = (const float*)d_in[5];
    const float* b1 = (const float*)d_in[6];
    const float* W2 = (const float*)d_in[7];
    const float* b2 = (const float*)d_in[8];
    float* out = (float*)d_out;
    int n_edges = in_sizes[1];

    constexpr int SMEM_BIG   = (64 * 132 + 128 * 132) * 4;  // 101376 B
    constexpr int SMEM_SMALL = (64 * 132 + 128 * 52) * 4;   //  60416 B
    static bool attr_done = false;
    if (!attr_done) {
        cudaFuncSetAttribute(gcn_gemm_kernel<128, 8, true, true>,
                             cudaFuncAttributeMaxDynamicSharedMemorySize, SMEM_BIG);
        cudaFuncSetAttribute(gcn_gemm_kernel<48, 3, false, false>,
                             cudaFuncAttributeMaxDynamicSharedMemorySize, SMEM_SMALL);
        attr_done = true;
    }

    int copy_blocks = (N_NODES * D / 4 + 255) / 256;
    int node_blocks = (N_NODES + 255) / 256;
    int edge_blocks = (n_edges + 255) / 256;
    int gath_blocks = (N_NODES + 7) / 8;      // 8 warps (nodes) per block
    int gemm_blocks = (N_NODES + 63) / 64;

    // Input copy + CSR build (once per launch)
    gcn_copy_kernel<<<copy_blocks, 256>>>(x);
    gcn_zero_cnt_kernel<<<node_blocks, 256>>>();
    gcn_hist_kernel<<<edge_blocks, 256>>>(dst, n_edges);
    gcn_scan_kernel<<<1, 1024>>>();
    gcn_fill_kernel<<<edge_blocks, 256>>>(src, dst, n_edges);

    // Layer 0
    gcn_gather_kernel<<<gath_blocks, 256>>>();
    gcn_gemm_kernel<128, 8, true, true><<<gemm_blocks, 256, SMEM_BIG>>>(
        W0, b0, nullptr, D, D);
    // Layer 1
    gcn_gather_kernel<<<gath_blocks, 256>>>();
    gcn_gemm_kernel<128, 8, true, true><<<gemm_blocks, 256, SMEM_BIG>>>(
        W1, b1, nullptr, D, D);
    // Layer 2 (head)
    gcn_gather_kernel<<<gath_blocks, 256>>>();
    gcn_gemm_kernel<48, 3, false, false><<<gemm_blocks, 256, SMEM_SMALL>>>(
        W2, b2, out, N_CLASSES, N_CLASSES);
}

// round 4
// speedup vs baseline: 1.4092x; 1.2700x over previous
#include <cuda_runtime.h>
#include <cuda_bf16.h>

#define N_NODES 50000
#define N_EDGES_MAX 600000
#define D 128
#define N_CLASSES 40

#define SCAN_BLK 1024
#define SCAN_NBLK ((N_NODES + SCAN_BLK - 1) / SCAN_BLK)   // 49

// Scratch (static device globals — no allocations allowed).
// Only referenced from DEVICE code (host shadow deref is silent on GB300/ATS).
__device__ float g_h[N_NODES * D];     // current layer activations
__device__ float g_acc[N_NODES * D];   // h + aggregated messages
__device__ int   g_cnt[N_NODES];       // in-degree histogram
__device__ int   g_row[N_NODES + 1];   // CSR row pointers (by dst)
__device__ int   g_cur[N_NODES];       // fill cursors
__device__ int   g_esrc[N_EDGES_MAX];  // CSR column indices (src nodes)
__device__ int   g_bsum[SCAN_NBLK];    // per-block scan totals

// ---------------------------------------------------------------------------
__global__ void gcn_copy_kernel(const float* __restrict__ x) {
    int i = blockIdx.x * blockDim.x + threadIdx.x;
    if (i < N_NODES * D / 4)
        ((float4*)g_h)[i] = ((const float4*)x)[i];
}

__global__ void gcn_zero_cnt_kernel() {
    int i = blockIdx.x * blockDim.x + threadIdx.x;
    if (i < N_NODES) g_cnt[i] = 0;
}

__global__ void gcn_hist_kernel(const int* __restrict__ dst, int n_edges) {
    int e = blockIdx.x * blockDim.x + threadIdx.x;
    if (e < n_edges) atomicAdd(&g_cnt[dst[e]], 1);
}

// Scan pass A: each block scans 1024 counts (exclusive, in-block) -> g_row,
// and writes its block total to g_bsum.
__global__ void gcn_scanA_kernel() {
    __shared__ int sh[SCAN_BLK];
    int t = threadIdx.x;
    int idx = blockIdx.x * SCAN_BLK + t;
    int v = (idx < N_NODES) ? g_cnt[idx] : 0;
    sh[t] = v;
    __syncthreads();
    // Hillis-Steele inclusive scan
    for (int off = 1; off < SCAN_BLK; off <<= 1) {
        int u = (t >= off) ? sh[t - off] : 0;
        __syncthreads();
        sh[t] += u;
        __syncthreads();
    }
    if (idx < N_NODES) g_row[idx] = sh[t] - v;   // exclusive within block
    if (t == SCAN_BLK - 1) g_bsum[blockIdx.x] = sh[t];
}

// Scan pass B: each block adds the exclusive prefix of block sums, writes g_cur,
// and the last element writes g_row[N_NODES].
__global__ void gcn_scanB_kernel() {
    int t = threadIdx.x;
    int blk = blockIdx.x;
    // exclusive prefix of g_bsum[0..blk) — tiny serial loop, L2-hot
    int off = 0;
    for (int b = 0; b < blk; b++) off += g_bsum[b];
    int idx = blk * SCAN_BLK + t;
    if (idx < N_NODES) {
        int r = g_row[idx] + off;
        g_row[idx] = r;
        g_cur[idx] = r;
        if (idx == N_NODES - 1) g_row[N_NODES] = r + g_cnt[idx];
    }
}

__global__ void gcn_fill_kernel(const int* __restrict__ src,
                                const int* __restrict__ dst, int n_edges) {
    int e = blockIdx.x * blockDim.x + threadIdx.x;
    if (e < n_edges) {
        int pos = atomicAdd(&g_cur[dst[e]], 1);
        g_esrc[pos] = src[e];
    }
}

// ---------------------------------------------------------------------------
// Gather: one warp per node. g_acc[n] = g_h[n] + sum_{s in nbrs(n)} g_h[s].
// ---------------------------------------------------------------------------
__global__ void gcn_gather_kernel() {
    int node = blockIdx.x * (blockDim.x >> 5) + (threadIdx.x >> 5);
    if (node >= N_NODES) return;
    int lane = threadIdx.x & 31;
    int beg = g_row[node];
    int end = g_row[node + 1];
    float4 acc = *(const float4*)(g_h + (size_t)node * D + lane * 4);  // self
    int i = beg;
    for (; i + 4 <= end; i += 4) {
        int s0 = g_esrc[i], s1 = g_esrc[i + 1], s2 = g_esrc[i + 2], s3 = g_esrc[i + 3];
        float4 v0 = *(const float4*)(g_h + (size_t)s0 * D + lane * 4);
        float4 v1 = *(const float4*)(g_h + (size_t)s1 * D + lane * 4);
        float4 v2 = *(const float4*)(g_h + (size_t)s2 * D + lane * 4);
        float4 v3 = *(const float4*)(g_h + (size_t)s3 * D + lane * 4);
        acc.x += v0.x + v1.x + v2.x + v3.x;
        acc.y += v0.y + v1.y + v2.y + v3.y;
        acc.z += v0.z + v1.z + v2.z + v3.z;
        acc.w += v0.w + v1.w + v2.w + v3.w;
    }
    for (; i < end; i++) {
        int s = g_esrc[i];
        float4 v = *(const float4*)(g_h + (size_t)s * D + lane * 4);
        acc.x += v.x; acc.y += v.y; acc.z += v.z; acc.w += v.w;
    }
    *(float4*)(g_acc + (size_t)node * D + lane * 4) = acc;
}

// ---------------------------------------------------------------------------
// Tiled fp32 GEMM: res[n, j] = act( sum_k g_acc[n,k] * W[j,k] + bias[j] )
// ---------------------------------------------------------------------------
template <int BN, int TN, bool RELU, bool TO_GH>
__global__ void gcn_gemm_kernel(const float* __restrict__ W,
                                const float* __restrict__ bias,
                                float* __restrict__ out,
                                int n_out, int ldo) {
    constexpr int BM = 64;
    constexpr int K = D;
    constexpr int LDA = K + 4;
    constexpr int LDB = BN + 4;
    extern __shared__ float sm[];
    float* As = sm;               // [BM][LDA]
    float* Bs = sm + BM * LDA;    // [K][LDB]

    int tid = threadIdx.x;
    int row0 = blockIdx.x * BM;

    for (int i = tid; i < BN * K; i += 256) {
        int j = i / K, k = i % K;
        float v = (j < n_out) ? __ldg(W + j * K + k) : 0.f;
        Bs[k * LDB + j] = v;
    }
    for (int i = tid * 4; i < BM * K; i += 256 * 4) {
        int r = i / K, k = i % K;
        int g = row0 + r;
        float4 v = (g < N_NODES) ? *(const float4*)(g_acc + (size_t)g * K + k)
                                 : make_float4(0.f, 0.f, 0.f, 0.f);
        *(float4*)(As + r * LDA + k) = v;
    }
    __syncthreads();

    int tc = tid & 15;
    int tr = tid >> 4;

    float acc[4][TN];
#pragma unroll
    for (int ii = 0; ii < 4; ii++)
#pragma unroll
        for (int jj = 0; jj < TN; jj++) acc[ii][jj] = 0.f;

#pragma unroll 4
    for (int k = 0; k < K; k++) {
        float a[4], b[TN];
#pragma unroll
        for (int ii = 0; ii < 4; ii++) a[ii] = As[(tr * 4 + ii) * LDA + k];
#pragma unroll
        for (int jj = 0; jj < TN; jj++) b[jj] = Bs[k * LDB + tc + 16 * jj];
#pragma unroll
        for (int ii = 0; ii < 4; ii++)
#pragma unroll
            for (int jj = 0; jj < TN; jj++)
                acc[ii][jj] = fmaf(a[ii], b[jj], acc[ii][jj]);
    }

#pragma unroll
    for (int ii = 0; ii < 4; ii++) {
        int g = row0 + tr * 4 + ii;
        if (g >= N_NODES) continue;
#pragma unroll
        for (int jj = 0; jj < TN; jj++) {
            int j = tc + 16 * jj;
            if (j >= n_out) continue;
            float v = acc[ii][jj] + __ldg(bias + j);
            if (RELU) v = fmaxf(v, 0.f);
            if (TO_GH) g_h[(size_t)g * D + j] = v;
            else       out[(size_t)g * ldo + j] = v;
        }
    }
}

// ---------------------------------------------------------------------------
extern "C" void kernel_launch(void* const* d_in, const int* in_sizes, int n_in,
                              void* d_out, int out_size) {
    const float* x  = (const float*)d_in[0];
    const int* src  = (const int*)d_in[1];
    const int* dst  = (const int*)d_in[2];
    const float* W0 = (const float*)d_in[3];
    const float* b0 = (const float*)d_in[4];
    const float* W1 = (const float*)d_in[5];
    const float* b1 = (const float*)d_in[6];
    const float* W2 = (const float*)d_in[7];
    const float* b2 = (const float*)d_in[8];
    float* out = (float*)d_out;
    int n_edges = in_sizes[1];

    constexpr int SMEM_BIG   = (64 * 132 + 128 * 132) * 4;  // 101376 B
    constexpr int SMEM_SMALL = (64 * 132 + 128 * 52) * 4;   //  60416 B
    static bool attr_done = false;
    if (!attr_done) {
        cudaFuncSetAttribute(gcn_gemm_kernel<128, 8, true, true>,
                             cudaFuncAttributeMaxDynamicSharedMemorySize, SMEM_BIG);
        cudaFuncSetAttribute(gcn_gemm_kernel<48, 3, false, false>,
                             cudaFuncAttributeMaxDynamicSharedMemorySize, SMEM_SMALL);
        attr_done = true;
    }

    int copy_blocks = (N_NODES * D / 4 + 255) / 256;
    int node_blocks = (N_NODES + 255) / 256;
    int edge_blocks = (n_edges + 255) / 256;
    int gath_blocks = (N_NODES + 7) / 8;      // 8 warps (nodes) per block
    int gemm_blocks = (N_NODES + 63) / 64;

    // Input copy + CSR build (once per launch)
    gcn_copy_kernel<<<copy_blocks, 256>>>(x);
    gcn_zero_cnt_kernel<<<node_blocks, 256>>>();
    gcn_hist_kernel<<<edge_blocks, 256>>>(dst, n_edges);
    gcn_scanA_kernel<<<SCAN_NBLK, SCAN_BLK>>>();
    gcn_scanB_kernel<<<SCAN_NBLK, SCAN_BLK>>>();
    gcn_fill_kernel<<<edge_blocks, 256>>>(src, dst, n_edges);

    // Layer 0
    gcn_gather_kernel<<<gath_blocks, 256>>>();
    gcn_gemm_kernel<128, 8, true, true><<<gemm_blocks, 256, SMEM_BIG>>>(
        W0, b0, nullptr, D, D);
    // Layer 1
    gcn_gather_kernel<<<gath_blocks, 256>>>();
    gcn_gemm_kernel<128, 8, true, true><<<gemm_blocks, 256, SMEM_BIG>>>(
        W1, b1, nullptr, D, D);
    // Layer 2 (head)
    gcn_gather_kernel<<<gath_blocks, 256>>>();
    gcn_gemm_kernel<48, 3, false, false><<<gemm_blocks, 256, SMEM_SMALL>>>(
        W2, b2, out, N_CLASSES, N_CLASSES);
}

// round 5
// speedup vs baseline: 1.5192x; 1.0781x over previous
#include <cuda_runtime.h>
#include <cuda_bf16.h>

#define N_NODES 50000
#define N_EDGES_MAX 600000
#define D 128
#define N_CLASSES 40

#define SCAN_BLK 1024
#define SCAN_NBLK ((N_NODES + SCAN_BLK - 1) / SCAN_BLK)   // 49

// Scratch (static device globals — no allocations allowed).
// Only referenced from DEVICE code (host shadow deref is silent on GB300/ATS).
__device__ float g_h[N_NODES * D];     // current layer activations
__device__ float g_acc[N_NODES * D];   // h + aggregated messages
__device__ int   g_cnt[N_NODES];       // in-degree histogram
__device__ int   g_row[N_NODES + 1];   // CSR row pointers (by dst)
__device__ int   g_cur[N_NODES];       // fill cursors
__device__ int   g_esrc[N_EDGES_MAX];  // CSR column indices (src nodes)
__device__ int   g_bsum[SCAN_NBLK];    // per-block scan totals

// ---------------------------------------------------------------------------
__global__ void gcn_copy_kernel(const float* __restrict__ x) {
    int i = blockIdx.x * blockDim.x + threadIdx.x;
    if (i < N_NODES * D / 4)
        ((float4*)g_h)[i] = ((const float4*)x)[i];
}

__global__ void gcn_zero_cnt_kernel() {
    int i = blockIdx.x * blockDim.x + threadIdx.x;
    if (i < N_NODES) g_cnt[i] = 0;
}

__global__ void gcn_hist_kernel(const int* __restrict__ dst, int n_edges) {
    int e = blockIdx.x * blockDim.x + threadIdx.x;
    if (e < n_edges) atomicAdd(&g_cnt[dst[e]], 1);
}

// Scan pass A: per-block exclusive scan of counts -> g_row, block total -> g_bsum.
__global__ void gcn_scanA_kernel() {
    __shared__ int sh[SCAN_BLK];
    int t = threadIdx.x;
    int idx = blockIdx.x * SCAN_BLK + t;
    int v = (idx < N_NODES) ? g_cnt[idx] : 0;
    sh[t] = v;
    __syncthreads();
    for (int off = 1; off < SCAN_BLK; off <<= 1) {
        int u = (t >= off) ? sh[t - off] : 0;
        __syncthreads();
        sh[t] += u;
        __syncthreads();
    }
    if (idx < N_NODES) g_row[idx] = sh[t] - v;
    if (t == SCAN_BLK - 1) g_bsum[blockIdx.x] = sh[t];
}

// Scan pass B: add exclusive prefix of block totals; also init g_cur.
__global__ void gcn_scanB_kernel() {
    int t = threadIdx.x;
    int blk = blockIdx.x;
    int off = 0;
    for (int b = 0; b < blk; b++) off += g_bsum[b];
    int idx = blk * SCAN_BLK + t;
    if (idx < N_NODES) {
        int r = g_row[idx] + off;
        g_row[idx] = r;
        g_cur[idx] = r;
        if (idx == N_NODES - 1) g_row[N_NODES] = r + g_cnt[idx];
    }
}

__global__ void gcn_fill_kernel(const int* __restrict__ src,
                                const int* __restrict__ dst, int n_edges) {
    int e = blockIdx.x * blockDim.x + threadIdx.x;
    if (e < n_edges) {
        int pos = atomicAdd(&g_cur[dst[e]], 1);
        g_esrc[pos] = src[e];
    }
}

// ---------------------------------------------------------------------------
// Gather: one warp per node. g_acc[n] = g_h[n] + sum_{s in nbrs(n)} g_h[s].
// ---------------------------------------------------------------------------
__global__ void gcn_gather_kernel() {
    int node = blockIdx.x * (blockDim.x >> 5) + (threadIdx.x >> 5);
    if (node >= N_NODES) return;
    int lane = threadIdx.x & 31;
    int beg = g_row[node];
    int end = g_row[node + 1];
    float4 acc = *(const float4*)(g_h + (size_t)node * D + lane * 4);  // self
    int i = beg;
    for (; i + 4 <= end; i += 4) {
        int s0 = g_esrc[i], s1 = g_esrc[i + 1], s2 = g_esrc[i + 2], s3 = g_esrc[i + 3];
        float4 v0 = *(const float4*)(g_h + (size_t)s0 * D + lane * 4);
        float4 v1 = *(const float4*)(g_h + (size_t)s1 * D + lane * 4);
        float4 v2 = *(const float4*)(g_h + (size_t)s2 * D + lane * 4);
        float4 v3 = *(const float4*)(g_h + (size_t)s3 * D + lane * 4);
        acc.x += v0.x + v1.x + v2.x + v3.x;
        acc.y += v0.y + v1.y + v2.y + v3.y;
        acc.z += v0.z + v1.z + v2.z + v3.z;
        acc.w += v0.w + v1.w + v2.w + v3.w;
    }
    for (; i < end; i++) {
        int s = g_esrc[i];
        float4 v = *(const float4*)(g_h + (size_t)s * D + lane * 4);
        acc.x += v.x; acc.y += v.y; acc.z += v.z; acc.w += v.w;
    }
    *(float4*)(g_acc + (size_t)node * D + lane * 4) = acc;
}

// ---------------------------------------------------------------------------
// Tiled fp32 GEMM using packed fma.rn.f32x2 (FFMA2, sm_100+):
//   res[n, j] = act( sum_k g_acc[n,k] * W[j,k] + bias[j] )
// Each thread: 4 rows x TNP column-PAIRS. Pair jj covers columns
// (2*tc + 32*jj, 2*tc + 32*jj + 1). 2 FMAs per issued instruction.
// ---------------------------------------------------------------------------
template <int BN, int TNP, bool RELU, bool TO_GH>
__global__ void gcn_gemm_kernel(const float* __restrict__ W,
                                const float* __restrict__ bias,
                                float* __restrict__ out,
                                int n_out, int ldo) {
    constexpr int BM = 64;
    constexpr int K = D;
    constexpr int LDA = K + 4;    // 132
    constexpr int LDB = BN + 8;   // even pad, 8B-aligned pair loads
    extern __shared__ float sm[];
    float* As = sm;               // [BM][LDA]
    float* Bs = sm + BM * LDA;    // [K][LDB]

    int tid = threadIdx.x;
    int row0 = blockIdx.x * BM;

    for (int i = tid; i < BN * K; i += 256) {
        int j = i / K, k = i % K;
        float v = (j < n_out) ? __ldg(W + j * K + k) : 0.f;
        Bs[k * LDB + j] = v;
    }
    for (int i = tid * 4; i < BM * K; i += 256 * 4) {
        int r = i / K, k = i % K;
        int g = row0 + r;
        float4 v = (g < N_NODES) ? *(const float4*)(g_acc + (size_t)g * K + k)
                                 : make_float4(0.f, 0.f, 0.f, 0.f);
        *(float4*)(As + r * LDA + k) = v;
    }
    __syncthreads();

    int tc = tid & 15;
    int tr = tid >> 4;

    unsigned long long acc[4][TNP];   // packed f32x2 accumulators
#pragma unroll
    for (int ii = 0; ii < 4; ii++)
#pragma unroll
        for (int jj = 0; jj < TNP; jj++) acc[ii][jj] = 0ULL;

#pragma unroll 4
    for (int k = 0; k < K; k++) {
        unsigned long long ap[4], bp[TNP];
#pragma unroll
        for (int ii = 0; ii < 4; ii++) {
            float a = As[(tr * 4 + ii) * LDA + k];
            asm("mov.b64 %0, {%1, %2};" : "=l"(ap[ii]) : "f"(a), "f"(a));
        }
#pragma unroll
        for (int jj = 0; jj < TNP; jj++)
            bp[jj] = *(const unsigned long long*)(Bs + k * LDB + 2 * tc + 32 * jj);
#pragma unroll
        for (int ii = 0; ii < 4; ii++)
#pragma unroll
            for (int jj = 0; jj < TNP; jj++)
                asm("fma.rn.f32x2 %0, %1, %2, %0;"
                    : "+l"(acc[ii][jj]) : "l"(ap[ii]), "l"(bp[jj]));
    }

#pragma unroll
    for (int ii = 0; ii < 4; ii++) {
        int g = row0 + tr * 4 + ii;
        if (g >= N_NODES) continue;
#pragma unroll
        for (int jj = 0; jj < TNP; jj++) {
            int j0 = 2 * tc + 32 * jj;
            float lo, hi;
            asm("mov.b64 {%0, %1}, %2;" : "=f"(lo), "=f"(hi) : "l"(acc[ii][jj]));
            if (j0 < n_out) {
                float v = lo + __ldg(bias + j0);
                if (RELU) v = fmaxf(v, 0.f);
                if (TO_GH) g_h[(size_t)g * D + j0] = v;
                else       out[(size_t)g * ldo + j0] = v;
            }
            if (j0 + 1 < n_out) {
                float v = hi + __ldg(bias + j0 + 1);
                if (RELU) v = fmaxf(v, 0.f);
                if (TO_GH) g_h[(size_t)g * D + j0 + 1] = v;
                else       out[(size_t)g * ldo + j0 + 1] = v;
            }
        }
    }
}

// ---------------------------------------------------------------------------
extern "C" void kernel_launch(void* const* d_in, const int* in_sizes, int n_in,
                              void* d_out, int out_size) {
    const float* x  = (const float*)d_in[0];
    const int* src  = (const int*)d_in[1];
    const int* dst  = (const int*)d_in[2];
    const float* W0 = (const float*)d_in[3];
    const float* b0 = (const float*)d_in[4];
    const float* W1 = (const float*)d_in[5];
    const float* b1 = (const float*)d_in[6];
    const float* W2 = (const float*)d_in[7];
    const float* b2 = (const float*)d_in[8];
    float* out = (float*)d_out;
    int n_edges = in_sizes[1];

    constexpr int SMEM_BIG   = (64 * 132 + 128 * 136) * 4;  // 103424 B
    constexpr int SMEM_SMALL = (64 * 132 + 128 * 72) * 4;   //  70656 B
    static bool attr_done = false;
    if (!attr_done) {
        cudaFuncSetAttribute(gcn_gemm_kernel<128, 4, true, true>,
                             cudaFuncAttributeMaxDynamicSharedMemorySize, SMEM_BIG);
        cudaFuncSetAttribute(gcn_gemm_kernel<64, 2, false, false>,
                             cudaFuncAttributeMaxDynamicSharedMemorySize, SMEM_SMALL);
        attr_done = true;
    }

    int copy_blocks = (N_NODES * D / 4 + 255) / 256;
    int node_blocks = (N_NODES + 255) / 256;
    int edge_blocks = (n_edges + 255) / 256;
    int gath_blocks = (N_NODES + 7) / 8;
    int gemm_blocks = (N_NODES + 63) / 64;

    // Input copy + CSR build (once per launch)
    gcn_copy_kernel<<<copy_blocks, 256>>>(x);
    gcn_zero_cnt_kernel<<<node_blocks, 256>>>();
    gcn_hist_kernel<<<edge_blocks, 256>>>(dst, n_edges);
    gcn_scanA_kernel<<<SCAN_NBLK, SCAN_BLK>>>();
    gcn_scanB_kernel<<<SCAN_NBLK, SCAN_BLK>>>();
    gcn_fill_kernel<<<edge_blocks, 256>>>(src, dst, n_edges);

    // Layer 0
    gcn_gather_kernel<<<gath_blocks, 256>>>();
    gcn_gemm_kernel<128, 4, true, true><<<gemm_blocks, 256, SMEM_BIG>>>(
        W0, b0, nullptr, D, D);
    // Layer 1
    gcn_gather_kernel<<<gath_blocks, 256>>>();
    gcn_gemm_kernel<128, 4, true, true><<<gemm_blocks, 256, SMEM_BIG>>>(
        W1, b1, nullptr, D, D);
    // Layer 2 (head)
    gcn_gather_kernel<<<gath_blocks, 256>>>();
    gcn_gemm_kernel<64, 2, false, false><<<gemm_blocks, 256, SMEM_SMALL>>>(
        W2, b2, out, N_CLASSES, N_CLASSES);
}